// round 14
// baseline (speedup 1.0000x reference)
#include <cuda_runtime.h>
#include <cuda_bf16.h>
#include <cstdint>

#define B_   32
#define S_   128
#define DAR  256
#define DENC 256
#define K_   12
#define N_   128
#define W_   116            // S - K
#define M_   (B_*W_)        // 3712
#define MT_  29
#define KSPL 1024           // 4 split-terms x 256
#define INV_E (1.0f/256.0f)

typedef unsigned long long ull;
typedef unsigned int u32;

// scratch (allocation-free rule: __device__ globals)
__device__ __align__(16) float g_locC[M_ * K_ * DENC];          // [m][k][e]
__device__ __align__(16) float g_part[24 * M_];                 // [j][site]
__device__ __align__(16) __nv_bfloat16 g_A2[M_ * KSPL];         // [m][1024]
__device__ __align__(16) __nv_bfloat16 g_B2[K_ * 256 * KSPL];   // [k*256+e][1024]

// ---------------- helpers ----------------
__device__ __forceinline__ ull pack2(float lo, float hi) {
    ull r; asm("mov.b64 %0, {%1, %2};" : "=l"(r) : "f"(lo), "f"(hi)); return r;
}
__device__ __forceinline__ void unpack2(float& lo, float& hi, ull v) {
    asm("mov.b64 {%0, %1}, %2;" : "=f"(lo), "=f"(hi) : "l"(v));
}
__device__ __forceinline__ ull fma2(ull a, ull b, ull c) {
    ull d; asm("fma.rn.f32x2 %0, %1, %2, %3;" : "=l"(d) : "l"(a), "l"(b), "l"(c)); return d;
}
__device__ __forceinline__ ull add2(ull a, ull b) {
    ull d; asm("add.rn.f32x2 %0, %1, %2;" : "=l"(d) : "l"(a), "l"(b)); return d;
}
__device__ __forceinline__ void cp_async16(void* dst, const void* src) {
    unsigned d = (unsigned)__cvta_generic_to_shared(dst);
    asm volatile("cp.async.cg.shared.global [%0], [%1], 16;" :: "r"(d), "l"(src));
}
__device__ __forceinline__ void cp_commit() { asm volatile("cp.async.commit_group;"); }
__device__ __forceinline__ void cp_wait0()  { asm volatile("cp.async.wait_group 0;"); }
__device__ __forceinline__ void cp_wait1()  { asm volatile("cp.async.wait_group 1;"); }
__device__ __forceinline__ void cp_wait2()  { asm volatile("cp.async.wait_group 2;"); }
__device__ __forceinline__ u32 smem_u32(const void* p) {
    u32 a; asm("{ .reg .u64 t; cvta.to.shared.u64 t, %1; cvt.u32.u64 %0, t; }"
               : "=r"(a) : "l"(p));
    return a;
}
__device__ __forceinline__ void ldsm4(u32* r, u32 addr) {
    asm volatile("ldmatrix.sync.aligned.m8n8.x4.shared.b16 {%0,%1,%2,%3}, [%4];"
                 : "=r"(r[0]), "=r"(r[1]), "=r"(r[2]), "=r"(r[3]) : "r"(addr));
}
__device__ __forceinline__ void mma16816(float* c, const u32* a, const u32* b) {
    asm volatile(
        "mma.sync.aligned.m16n8k16.row.col.f32.bf16.bf16.f32 "
        "{%0,%1,%2,%3}, {%4,%5,%6,%7}, {%8,%9}, {%0,%1,%2,%3};"
        : "+f"(c[0]), "+f"(c[1]), "+f"(c[2]), "+f"(c[3])
        : "r"(a[0]), "r"(a[1]), "r"(a[2]), "r"(a[3]), "r"(b[0]), "r"(b[1]));
}

// ---------------------------------------------------------------------------
// kP: 2-way bf16 split -> A'/B' with 4-term K concatenation (R12 exact)
// ---------------------------------------------------------------------------
#define A_CTAS 464      // 3712/8
__global__ __launch_bounds__(256) void kP(const float* __restrict__ cF,
                                          const float* __restrict__ Wp) {
    const int blk = blockIdx.x;
    const int lrow = threadIdx.x >> 5;
    const int piece = threadIdx.x & 31;

    const float* src;
    __nv_bfloat16* dstRow;
    int ta[4];
    if (blk < A_CTAS) {
        int m = blk * 8 + lrow;
        int b = m / W_, w = m - b * W_;
        src = cF + (size_t)(b * S_ + w) * DAR;
        dstRow = g_A2 + (size_t)m * KSPL;
        ta[0] = 0; ta[1] = 0; ta[2] = 1; ta[3] = 1;
    } else {
        int row = (blk - A_CTAS) * 8 + lrow;
        int k = row >> 8, e = row & 255;
        src = Wp + ((size_t)k * DENC + e) * DAR;
        dstRow = g_B2 + (size_t)row * KSPL;
        ta[0] = 0; ta[1] = 1; ta[2] = 0; ta[3] = 1;
    }

    float4 x0 = *(const float4*)(src + piece * 8);
    float4 x1 = *(const float4*)(src + piece * 8 + 4);
    float xs[8] = {x0.x, x0.y, x0.z, x0.w, x1.x, x1.y, x1.z, x1.w};

    u32 sp[2][4];
    #pragma unroll
    for (int q = 0; q < 4; q++) {
        unsigned short h[2][2];
        #pragma unroll
        for (int d = 0; d < 2; d++) {
            float x = xs[2 * q + d];
            __nv_bfloat16 v1 = __float2bfloat16(x);
            __nv_bfloat16 v2 = __float2bfloat16(x - __bfloat162float(v1));
            h[0][d] = __bfloat16_as_ushort(v1);
            h[1][d] = __bfloat16_as_ushort(v2);
        }
        #pragma unroll
        for (int l = 0; l < 2; l++)
            sp[l][q] = ((u32)h[l][1] << 16) | h[l][0];
    }

    #pragma unroll
    for (int t = 0; t < 4; t++) {
        uint4 v = make_uint4(sp[ta[t]][0], sp[ta[t]][1], sp[ta[t]][2], sp[ta[t]][3]);
        *(uint4*)(dstRow + t * 256 + piece * 8) = v;
    }
}

// ---------------------------------------------------------------------------
// kA: bf16 mma.sync GEMM, 3-stage cp.async pipeline, 2 CTAs/SM (R12 exact)
// ---------------------------------------------------------------------------
#define ROWB 144
#define STG_BYTES (128 * ROWB * 2)      // 36864
#define KA_SMEM (3 * STG_BYTES)         // 110592
#define NCHUNK 16

__global__ __launch_bounds__(256, 2) void kA() {
    extern __shared__ __align__(16) unsigned char smA[];
    const int tid = threadIdx.x, w = tid >> 5, lane = tid & 31;
    const int mt = blockIdx.x, et = blockIdx.y, k = blockIdx.z;
    const u32 sb = smem_u32(smA);

    const __nv_bfloat16* Ag = g_A2 + (size_t)(mt * 128) * KSPL;
    const __nv_bfloat16* Bg = g_B2 + (size_t)(k * 256 + et * 128) * KSPL;

    float acc[2][8][4];
    #pragma unroll
    for (int i = 0; i < 2; i++)
        #pragma unroll
        for (int n = 0; n < 8; n++)
            #pragma unroll
            for (int q = 0; q < 4; q++) acc[i][n][q] = 0.f;

    auto issue = [&](int c, int buf) {
        unsigned char* base = smA + buf * STG_BYTES;
        #pragma unroll
        for (int j = 0; j < 4; j++) {
            int seg = tid + j * 256;
            int row = seg >> 3, pc = seg & 7;
            cp_async16(base + row * ROWB + pc * 16,
                       Ag + (size_t)row * KSPL + c * 64 + pc * 8);
        }
        #pragma unroll
        for (int j = 0; j < 4; j++) {
            int seg = tid + j * 256;
            int row = seg >> 3, pc = seg & 7;
            cp_async16(base + 128 * ROWB + row * ROWB + pc * 16,
                       Bg + (size_t)row * KSPL + c * 64 + pc * 8);
        }
        cp_commit();
    };

    issue(0, 0); issue(1, 1); issue(2, 2);

    const u32 aRowSel = (lane & 15);
    const u32 aHalf   = (lane >> 4);
    const u32 bRowSel = (lane & 7) + ((lane >> 4) << 3);
    const u32 bHalf   = (lane >> 3) & 1;

    for (int c = 0; c < NCHUNK; c++) {
        if (c <= NCHUNK - 3) cp_wait2();
        else if (c == NCHUNK - 2) cp_wait1();
        else cp_wait0();
        __syncthreads();

        const u32 Abase = sb + (c % 3) * STG_BYTES;
        const u32 Bbase = Abase + 128 * ROWB;

        #pragma unroll
        for (int ks = 0; ks < 4; ks++) {
            u32 afr[2][4];
            #pragma unroll
            for (int mtile = 0; mtile < 2; mtile++) {
                u32 addr = Abase + ((w & 3) * 32 + mtile * 16 + aRowSel) * ROWB
                         + aHalf * 16 + ks * 32;
                ldsm4(afr[mtile], addr);
            }
            u32 bfr[4][4];
            #pragma unroll
            for (int nt2 = 0; nt2 < 4; nt2++) {
                u32 addr = Bbase + ((w >> 2) * 64 + nt2 * 16 + bRowSel) * ROWB
                         + bHalf * 16 + ks * 32;
                ldsm4(bfr[nt2], addr);
            }
            #pragma unroll
            for (int mtile = 0; mtile < 2; mtile++)
                #pragma unroll
                for (int nt = 0; nt < 8; nt++)
                    mma16816(acc[mtile][nt], afr[mtile], &bfr[nt >> 1][(nt & 1) * 2]);
        }
        __syncthreads();
        if (c < NCHUNK - 3) issue(c + 3, (c + 3) % 3);
    }

    const int mW = mt * 128 + (w & 3) * 32 + (lane >> 2);
    const int eW = et * 128 + (w >> 2) * 64 + (lane & 3) * 2;
    #pragma unroll
    for (int mtile = 0; mtile < 2; mtile++) {
        #pragma unroll
        for (int nt = 0; nt < 8; nt++) {
            int m0 = mW + mtile * 16;
            int e0 = eW + nt * 8;
            float* d0 = g_locC + ((size_t)m0 * K_ + k) * 256 + e0;
            float* d1 = g_locC + ((size_t)(m0 + 8) * K_ + k) * 256 + e0;
            *(float2*)d0 = make_float2(acc[mtile][nt][0], acc[mtile][nt][1]);
            *(float2*)d1 = make_float2(acc[mtile][nt][2], acc[mtile][nt][3]);
        }
    }
}

// ---------------------------------------------------------------------------
// kB v5 (fixed): e-chunked (4 x 64), warp-local cp.async pipeline, 4 rows/thr.
// locC read key now matches store key: key(e) = (e>>5)<<1, e = c*64+es*8+j*4+d
// ---------------------------------------------------------------------------
#define ECH 64
#define RS  64
#define STAGE_F (144 * RS)                              // 9216 floats
#define KB_LOCC_OFF (2 * STAGE_F)                       // 18432
#define KB_SC_OFF   (KB_LOCC_OFF + 256 * 16)            // 22528
#define KB_SMEM_FLOATS (KB_SC_OFF + K_ * 144)           // 24256
#define KB_SMEM (KB_SMEM_FLOATS * 4)                    // 97024 B

__global__ __launch_bounds__(288, 2) void kB(const float* __restrict__ enc,
                                             const void* __restrict__ extIdxRaw) {
    extern __shared__ __align__(16) float smB[];
    float* stages = smB;                     // [2][144][64] swizzled
    float* locC_t = smB + KB_LOCC_OFF;       // [e][k^key(e)] stride 16
    float* scores = smB + KB_SC_OFF;         // [k][144]

    const int blk = blockIdx.x;
    const int b = blk / W_, w = blk - b * W_;
    const int tid = threadIdx.x;
    const int wp = tid >> 5, lane = tid & 31;
    const int es = lane >> 2, ng = lane & 3;

    // extIdx dtype detection (int64 -> odd 32-bit words all zero)
    const int* p32 = (const int*)extIdxRaw;
    int orv = 0;
    #pragma unroll
    for (int q = 0; q < 16; q++) orv |= p32[2 * q + 1];
    const bool is64 = (orv == 0);
    const long long* p64 = (const long long*)extIdxRaw;

    int myRow = 0;
    if (lane < 16) {
        int r = wp * 16 + lane;
        if (r < 128) {
            size_t j = (size_t)(b * N_ + r) * W_ + w;
            int idx = is64 ? (int)p64[j] : p32[j];
            myRow = idx & (B_ * S_ - 1);
        } else if (r < 140) {
            myRow = b * S_ + (r - 128) + 1 + w;
        }
    }

    auto stage = [&](int c, int buf) {
        const float* encC = enc + c * ECH;
        #pragma unroll
        for (int j = 0; j < 8; j++) {
            int t = j * 32 + lane;             // 0..255
            int riw = t >> 4;                  // 0..15
            int p = t & 15;                    // 16B piece
            int sr = __shfl_sync(0xffffffffu, myRow, riw);
            int rr = wp * 16 + riw;
            float* dst = stages + buf * STAGE_F + rr * RS + ((p ^ (rr & 7)) << 2);
            cp_async16(dst, encC + (size_t)sr * DENC + p * 4);
        }
        cp_commit();
    };

    stage(0, 0);
    stage(1, 1);

    // locC tile: locC_t[e*16 + (k ^ ((e>>5)<<1))]
    const float* lcg = g_locC + (size_t)blk * (K_ * 256);
    for (int q = tid; q < K_ * 256; q += 288) {
        int k = q >> 8, e = q & 255;
        locC_t[e * 16 + (k ^ ((e >> 5) << 1))] = lcg[q];
    }
    __syncthreads();    // locC visible to all warps

    int rr_t[4];
    #pragma unroll
    for (int i = 0; i < 4; i++) rr_t[i] = wp * 16 + ng + 4 * i;

    ull acc[6][4];
    #pragma unroll
    for (int kp = 0; kp < 6; kp++)
        #pragma unroll
        for (int i = 0; i < 4; i++) acc[kp][i] = 0ull;

    for (int c = 0; c < 4; c++) {
        if (c < 3) cp_wait1(); else cp_wait0();
        __syncwarp();
        const float* rbuf = stages + (c & 1) * STAGE_F;
        // store key for e = c*64 + es*8 + ... : (e>>5)<<1 = (2c + (es>>2))<<1
        const int swc = ((2 * c + (es >> 2)) << 1);

        #pragma unroll
        for (int j = 0; j < 2; j++) {
            const int q = 2 * es + j;
            float4 cur[4];
            #pragma unroll
            for (int i = 0; i < 4; i++)
                cur[i] = *(const float4*)(rbuf + rr_t[i] * RS + ((q ^ (rr_t[i] & 7)) << 2));
            #pragma unroll
            for (int d = 0; d < 4; d++) {
                const float* lcb = locC_t + (c * 64 + es * 8 + j * 4 + d) * 16;
                ull lc[6];
                #pragma unroll
                for (int kp = 0; kp < 6; kp++) lc[kp] = *(const ull*)(lcb + ((2 * kp) ^ swc));
                #pragma unroll
                for (int i = 0; i < 4; i++) {
                    float v = (d == 0) ? cur[i].x : (d == 1) ? cur[i].y
                            : (d == 2) ? cur[i].z : cur[i].w;
                    ull b2 = pack2(v, v);
                    #pragma unroll
                    for (int kp = 0; kp < 6; kp++)
                        acc[kp][i] = fma2(lc[kp], b2, acc[kp][i]);
                }
            }
        }
        if (c < 2) stage(c + 2, c & 1);
    }

    // butterfly-reduce the 8 e-splits (lane bits 2,3,4)
    #pragma unroll
    for (int off = 4; off <= 16; off <<= 1)
        #pragma unroll
        for (int kp = 0; kp < 6; kp++)
            #pragma unroll
            for (int i = 0; i < 4; i++)
                acc[kp][i] = add2(acc[kp][i], __shfl_xor_sync(0xffffffffu, acc[kp][i], off));

    if (es == 0) {
        #pragma unroll
        for (int i = 0; i < 4; i++) {
            int r = rr_t[i];
            if (r < 140) {
                #pragma unroll
                for (int kp = 0; kp < 6; kp++) {
                    float s0, s1; unpack2(s0, s1, acc[kp][i]);
                    scores[(2 * kp) * 144 + r]     = s0;
                    scores[(2 * kp + 1) * 144 + r] = s1;
                }
            }
        }
    }
    __syncthreads();

    // per-k logsumexp over [pos, 128 negs]; 9 warps cover 12 k
    for (int k = wp; k < K_; k += 9) {
        float v[4], mx = -1e30f;
        #pragma unroll
        for (int q = 0; q < 4; q++) {
            v[q] = scores[k * 144 + lane + q * 32] * INV_E;
            mx = fmaxf(mx, v[q]);
        }
        #pragma unroll
        for (int off = 16; off > 0; off >>= 1)
            mx = fmaxf(mx, __shfl_xor_sync(0xffffffffu, mx, off));
        const float pos = scores[k * 144 + 128 + k] * INV_E;
        const float mm = fmaxf(mx, pos);
        float se = 0.f;
        #pragma unroll
        for (int q = 0; q < 4; q++) se += __expf(v[q] - mm);
        #pragma unroll
        for (int off = 16; off > 0; off >>= 1)
            se += __shfl_xor_sync(0xffffffffu, se, off);
        if (lane == 0) {
            float lse = mm + __logf(se + __expf(pos - mm));
            g_part[(size_t)k * M_ + blk]        = lse - pos;
            g_part[(size_t)(12 + k) * M_ + blk] = (pos >= mx) ? 1.f : 0.f;
        }
    }
}

// ---------------------------------------------------------------------------
// kC: 24 blocks x 512 threads, contiguous segment sums
// ---------------------------------------------------------------------------
__global__ __launch_bounds__(512) void kC(float* __restrict__ out) {
    __shared__ float red[16];
    const int j = blockIdx.x;
    const int tid = threadIdx.x, lane = tid & 31, wp = tid >> 5;
    const float* src = g_part + (size_t)j * M_;
    float s = 0.f;
    for (int i = tid; i < M_; i += 512) s += src[i];
    #pragma unroll
    for (int off = 16; off > 0; off >>= 1)
        s += __shfl_xor_sync(0xffffffffu, s, off);
    if (lane == 0) red[wp] = s;
    __syncthreads();
    if (tid < 16) {
        float v = red[tid];
        #pragma unroll
        for (int off = 8; off > 0; off >>= 1)
            v += __shfl_xor_sync(0xffffu, v, off);
        if (tid == 0) out[j] = v * (1.0f / (float)M_);
    }
}

// ---------------------------------------------------------------------------
extern "C" void kernel_launch(void* const* d_in, const int* in_sizes, int n_in,
                              void* d_out, int out_size) {
    const float* cF  = (const float*)d_in[0];
    const float* enc = (const float*)d_in[1];
    const float* Wp  = (const float*)d_in[2];
    const void* eIdx = (const void*)d_in[3];
    float* out = (float*)d_out;

    cudaFuncSetAttribute(kA, cudaFuncAttributeMaxDynamicSharedMemorySize, KA_SMEM);
    cudaFuncSetAttribute(kB, cudaFuncAttributeMaxDynamicSharedMemorySize, KB_SMEM);

    kP<<<A_CTAS + 384, 256>>>(cF, Wp);
    dim3 gA(MT_, 2, K_);
    kA<<<gA, 256, KA_SMEM>>>();
    kB<<<M_, 288, KB_SMEM>>>(enc, eIdx);
    kC<<<24, 512>>>(out);
}

// round 15
// speedup vs baseline: 1.3345x; 1.3345x over previous
#include <cuda_runtime.h>
#include <cuda_bf16.h>
#include <cstdint>

#define B_   32
#define S_   128
#define DAR  256
#define DENC 256
#define K_   12
#define N_   128
#define W_   116            // S - K
#define M_   (B_*W_)        // 3712
#define MT_  29
#define KSPL 1024           // 4 split-terms x 256
#define INV_E (1.0f/256.0f)

typedef unsigned long long ull;
typedef unsigned int u32;

// scratch (allocation-free rule: __device__ globals)
__device__ __align__(16) float g_locC[M_ * K_ * DENC];          // [m][k][e]
__device__ __align__(16) float g_part[24 * M_];                 // [j][site]
__device__ __align__(16) __nv_bfloat16 g_A2[M_ * KSPL];         // [m][1024]
__device__ __align__(16) __nv_bfloat16 g_B2[K_ * 256 * KSPL];   // [k*256+e][1024]

// ---------------- helpers ----------------
__device__ __forceinline__ ull pack2(float lo, float hi) {
    ull r; asm("mov.b64 %0, {%1, %2};" : "=l"(r) : "f"(lo), "f"(hi)); return r;
}
__device__ __forceinline__ void unpack2(float& lo, float& hi, ull v) {
    asm("mov.b64 {%0, %1}, %2;" : "=f"(lo), "=f"(hi) : "l"(v));
}
__device__ __forceinline__ ull fma2(ull a, ull b, ull c) {
    ull d; asm("fma.rn.f32x2 %0, %1, %2, %3;" : "=l"(d) : "l"(a), "l"(b), "l"(c)); return d;
}
__device__ __forceinline__ ull add2(ull a, ull b) {
    ull d; asm("add.rn.f32x2 %0, %1, %2;" : "=l"(d) : "l"(a), "l"(b)); return d;
}
__device__ __forceinline__ void cp_async16(void* dst, const void* src) {
    unsigned d = (unsigned)__cvta_generic_to_shared(dst);
    asm volatile("cp.async.cg.shared.global [%0], [%1], 16;" :: "r"(d), "l"(src));
}
__device__ __forceinline__ void cp_commit() { asm volatile("cp.async.commit_group;"); }
__device__ __forceinline__ void cp_wait0()  { asm volatile("cp.async.wait_group 0;"); }
__device__ __forceinline__ void cp_wait1()  { asm volatile("cp.async.wait_group 1;"); }
__device__ __forceinline__ void cp_wait2()  { asm volatile("cp.async.wait_group 2;"); }
__device__ __forceinline__ u32 smem_u32(const void* p) {
    u32 a; asm("{ .reg .u64 t; cvta.to.shared.u64 t, %1; cvt.u32.u64 %0, t; }"
               : "=r"(a) : "l"(p));
    return a;
}
__device__ __forceinline__ void ldsm4(u32* r, u32 addr) {
    asm volatile("ldmatrix.sync.aligned.m8n8.x4.shared.b16 {%0,%1,%2,%3}, [%4];"
                 : "=r"(r[0]), "=r"(r[1]), "=r"(r[2]), "=r"(r[3]) : "r"(addr));
}
__device__ __forceinline__ void mma16816(float* c, const u32* a, const u32* b) {
    asm volatile(
        "mma.sync.aligned.m16n8k16.row.col.f32.bf16.bf16.f32 "
        "{%0,%1,%2,%3}, {%4,%5,%6,%7}, {%8,%9}, {%0,%1,%2,%3};"
        : "+f"(c[0]), "+f"(c[1]), "+f"(c[2]), "+f"(c[3])
        : "r"(a[0]), "r"(a[1]), "r"(a[2]), "r"(a[3]), "r"(b[0]), "r"(b[1]));
}

// ---------------------------------------------------------------------------
// kP: 2-way bf16 split -> A'/B' with 4-term K concatenation (R12 exact)
// ---------------------------------------------------------------------------
#define A_CTAS 464      // 3712/8
__global__ __launch_bounds__(256) void kP(const float* __restrict__ cF,
                                          const float* __restrict__ Wp) {
    const int blk = blockIdx.x;
    const int lrow = threadIdx.x >> 5;
    const int piece = threadIdx.x & 31;

    const float* src;
    __nv_bfloat16* dstRow;
    int ta[4];
    if (blk < A_CTAS) {
        int m = blk * 8 + lrow;
        int b = m / W_, w = m - b * W_;
        src = cF + (size_t)(b * S_ + w) * DAR;
        dstRow = g_A2 + (size_t)m * KSPL;
        ta[0] = 0; ta[1] = 0; ta[2] = 1; ta[3] = 1;
    } else {
        int row = (blk - A_CTAS) * 8 + lrow;
        int k = row >> 8, e = row & 255;
        src = Wp + ((size_t)k * DENC + e) * DAR;
        dstRow = g_B2 + (size_t)row * KSPL;
        ta[0] = 0; ta[1] = 1; ta[2] = 0; ta[3] = 1;
    }

    float4 x0 = *(const float4*)(src + piece * 8);
    float4 x1 = *(const float4*)(src + piece * 8 + 4);
    float xs[8] = {x0.x, x0.y, x0.z, x0.w, x1.x, x1.y, x1.z, x1.w};

    u32 sp[2][4];
    #pragma unroll
    for (int q = 0; q < 4; q++) {
        unsigned short h[2][2];
        #pragma unroll
        for (int d = 0; d < 2; d++) {
            float x = xs[2 * q + d];
            __nv_bfloat16 v1 = __float2bfloat16(x);
            __nv_bfloat16 v2 = __float2bfloat16(x - __bfloat162float(v1));
            h[0][d] = __bfloat16_as_ushort(v1);
            h[1][d] = __bfloat16_as_ushort(v2);
        }
        #pragma unroll
        for (int l = 0; l < 2; l++)
            sp[l][q] = ((u32)h[l][1] << 16) | h[l][0];
    }

    #pragma unroll
    for (int t = 0; t < 4; t++) {
        uint4 v = make_uint4(sp[ta[t]][0], sp[ta[t]][1], sp[ta[t]][2], sp[ta[t]][3]);
        *(uint4*)(dstRow + t * 256 + piece * 8) = v;
    }
}

// ---------------------------------------------------------------------------
// kA: bf16 mma.sync GEMM, 3-stage cp.async pipeline, 2 CTAs/SM (R12 exact)
// ---------------------------------------------------------------------------
#define ROWB 144
#define STG_BYTES (128 * ROWB * 2)      // 36864
#define KA_SMEM (3 * STG_BYTES)         // 110592
#define NCHUNK 16

__global__ __launch_bounds__(256, 2) void kA() {
    extern __shared__ __align__(16) unsigned char smA[];
    const int tid = threadIdx.x, w = tid >> 5, lane = tid & 31;
    const int mt = blockIdx.x, et = blockIdx.y, k = blockIdx.z;
    const u32 sb = smem_u32(smA);

    const __nv_bfloat16* Ag = g_A2 + (size_t)(mt * 128) * KSPL;
    const __nv_bfloat16* Bg = g_B2 + (size_t)(k * 256 + et * 128) * KSPL;

    float acc[2][8][4];
    #pragma unroll
    for (int i = 0; i < 2; i++)
        #pragma unroll
        for (int n = 0; n < 8; n++)
            #pragma unroll
            for (int q = 0; q < 4; q++) acc[i][n][q] = 0.f;

    auto issue = [&](int c, int buf) {
        unsigned char* base = smA + buf * STG_BYTES;
        #pragma unroll
        for (int j = 0; j < 4; j++) {
            int seg = tid + j * 256;
            int row = seg >> 3, pc = seg & 7;
            cp_async16(base + row * ROWB + pc * 16,
                       Ag + (size_t)row * KSPL + c * 64 + pc * 8);
        }
        #pragma unroll
        for (int j = 0; j < 4; j++) {
            int seg = tid + j * 256;
            int row = seg >> 3, pc = seg & 7;
            cp_async16(base + 128 * ROWB + row * ROWB + pc * 16,
                       Bg + (size_t)row * KSPL + c * 64 + pc * 8);
        }
        cp_commit();
    };

    issue(0, 0); issue(1, 1); issue(2, 2);

    const u32 aRowSel = (lane & 15);
    const u32 aHalf   = (lane >> 4);
    const u32 bRowSel = (lane & 7) + ((lane >> 4) << 3);
    const u32 bHalf   = (lane >> 3) & 1;

    for (int c = 0; c < NCHUNK; c++) {
        if (c <= NCHUNK - 3) cp_wait2();
        else if (c == NCHUNK - 2) cp_wait1();
        else cp_wait0();
        __syncthreads();

        const u32 Abase = sb + (c % 3) * STG_BYTES;
        const u32 Bbase = Abase + 128 * ROWB;

        #pragma unroll
        for (int ks = 0; ks < 4; ks++) {
            u32 afr[2][4];
            #pragma unroll
            for (int mtile = 0; mtile < 2; mtile++) {
                u32 addr = Abase + ((w & 3) * 32 + mtile * 16 + aRowSel) * ROWB
                         + aHalf * 16 + ks * 32;
                ldsm4(afr[mtile], addr);
            }
            u32 bfr[4][4];
            #pragma unroll
            for (int nt2 = 0; nt2 < 4; nt2++) {
                u32 addr = Bbase + ((w >> 2) * 64 + nt2 * 16 + bRowSel) * ROWB
                         + bHalf * 16 + ks * 32;
                ldsm4(bfr[nt2], addr);
            }
            #pragma unroll
            for (int mtile = 0; mtile < 2; mtile++)
                #pragma unroll
                for (int nt = 0; nt < 8; nt++)
                    mma16816(acc[mtile][nt], afr[mtile], &bfr[nt >> 1][(nt & 1) * 2]);
        }
        __syncthreads();
        if (c < NCHUNK - 3) issue(c + 3, (c + 3) % 3);
    }

    const int mW = mt * 128 + (w & 3) * 32 + (lane >> 2);
    const int eW = et * 128 + (w >> 2) * 64 + (lane & 3) * 2;
    #pragma unroll
    for (int mtile = 0; mtile < 2; mtile++) {
        #pragma unroll
        for (int nt = 0; nt < 8; nt++) {
            int m0 = mW + mtile * 16;
            int e0 = eW + nt * 8;
            float* d0 = g_locC + ((size_t)m0 * K_ + k) * 256 + e0;
            float* d1 = g_locC + ((size_t)(m0 + 8) * K_ + k) * 256 + e0;
            *(float2*)d0 = make_float2(acc[mtile][nt][0], acc[mtile][nt][1]);
            *(float2*)d1 = make_float2(acc[mtile][nt][2], acc[mtile][nt][3]);
        }
    }
}

// ---------------------------------------------------------------------------
// kB v6: e-chunked (4 x 64), warp-local cp.async pipeline, 2 rows/thread.
// lane: es = lane>>3 (4 e-slices of 16), ng = lane&7. rows = 16wp + ng + 8i.
// Per-phase analysis: row LDS.128 hits 8 distinct bank-groups (ng spans rr&7),
// lc LDS.64 is phase-broadcast. locC key = ((e>>4)&7)<<1 (store == load).
// ---------------------------------------------------------------------------
#define ECH 64
#define RS  64
#define STAGE_F (144 * RS)                              // 9216 floats
#define KB_LOCC_OFF (2 * STAGE_F)                       // 18432
#define KB_SC_OFF   (KB_LOCC_OFF + 256 * 16)            // 22528
#define KB_SMEM_FLOATS (KB_SC_OFF + K_ * 144)           // 24256
#define KB_SMEM (KB_SMEM_FLOATS * 4)                    // 97024 B

__global__ __launch_bounds__(288, 2) void kB(const float* __restrict__ enc,
                                             const void* __restrict__ extIdxRaw) {
    extern __shared__ __align__(16) float smB[];
    float* stages = smB;                     // [2][144][64] swizzled
    float* locC_t = smB + KB_LOCC_OFF;       // [e][k^key(e)] stride 16
    float* scores = smB + KB_SC_OFF;         // [k][144]

    const int blk = blockIdx.x;
    const int b = blk / W_, w = blk - b * W_;
    const int tid = threadIdx.x;
    const int wp = tid >> 5, lane = tid & 31;
    const int es = lane >> 3, ng = lane & 7;

    // extIdx dtype detection (int64 -> odd 32-bit words all zero)
    const int* p32 = (const int*)extIdxRaw;
    int orv = 0;
    #pragma unroll
    for (int q = 0; q < 16; q++) orv |= p32[2 * q + 1];
    const bool is64 = (orv == 0);
    const long long* p64 = (const long long*)extIdxRaw;

    int myRow = 0;
    if (lane < 16) {
        int r = wp * 16 + lane;
        if (r < 128) {
            size_t j = (size_t)(b * N_ + r) * W_ + w;
            int idx = is64 ? (int)p64[j] : p32[j];
            myRow = idx & (B_ * S_ - 1);
        } else if (r < 140) {
            myRow = b * S_ + (r - 128) + 1 + w;
        }
    }

    auto stage = [&](int c, int buf) {
        const float* encC = enc + c * ECH;
        #pragma unroll
        for (int j = 0; j < 8; j++) {
            int t = j * 32 + lane;             // 0..255
            int riw = t >> 4;                  // 0..15
            int p = t & 15;                    // 16B piece
            int sr = __shfl_sync(0xffffffffu, myRow, riw);
            int rr = wp * 16 + riw;
            float* dst = stages + buf * STAGE_F + rr * RS + ((p ^ (rr & 7)) << 2);
            cp_async16(dst, encC + (size_t)sr * DENC + p * 4);
        }
        cp_commit();
    };

    stage(0, 0);
    stage(1, 1);

    // locC tile: locC_t[e*16 + (k ^ (((e>>4)&7)<<1))]
    const float* lcg = g_locC + (size_t)blk * (K_ * 256);
    for (int q = tid; q < K_ * 256; q += 288) {
        int k = q >> 8, e = q & 255;
        locC_t[e * 16 + (k ^ (((e >> 4) & 7) << 1))] = lcg[q];
    }
    __syncthreads();    // locC visible to all warps

    const int rr0 = wp * 16 + ng;              // rows rr0, rr0+8
    const int key0 = rr0 & 7;                  // == (rr0+8)&7

    ull acc[6][2];
    #pragma unroll
    for (int kp = 0; kp < 6; kp++) { acc[kp][0] = 0ull; acc[kp][1] = 0ull; }

    for (int c = 0; c < 4; c++) {
        if (c < 3) cp_wait1(); else cp_wait0();
        __syncwarp();
        const float* rbuf = stages + (c & 1) * STAGE_F;
        const int swc = ((4 * c + es) & 7) << 1;   // key for e>>4 = 4c+es

        #pragma unroll
        for (int j = 0; j < 4; j++) {
            const int q = 4 * es + j;              // piece within row-chunk
            float4 cur0 = *(const float4*)(rbuf + rr0 * RS + ((q ^ key0) << 2));
            float4 cur1 = *(const float4*)(rbuf + (rr0 + 8) * RS + ((q ^ key0) << 2));
            #pragma unroll
            for (int d = 0; d < 4; d++) {
                const float* lcb = locC_t + (c * 64 + es * 16 + j * 4 + d) * 16;
                ull lc[6];
                #pragma unroll
                for (int kp = 0; kp < 6; kp++) lc[kp] = *(const ull*)(lcb + ((2 * kp) ^ swc));
                float v0 = (d == 0) ? cur0.x : (d == 1) ? cur0.y : (d == 2) ? cur0.z : cur0.w;
                float v1 = (d == 0) ? cur1.x : (d == 1) ? cur1.y : (d == 2) ? cur1.z : cur1.w;
                ull b0 = pack2(v0, v0), b1 = pack2(v1, v1);
                #pragma unroll
                for (int kp = 0; kp < 6; kp++) {
                    acc[kp][0] = fma2(lc[kp], b0, acc[kp][0]);
                    acc[kp][1] = fma2(lc[kp], b1, acc[kp][1]);
                }
            }
        }
        if (c < 2) stage(c + 2, c & 1);
    }

    // butterfly-reduce the 4 e-splits (lane bits 3,4)
    #pragma unroll
    for (int off = 8; off <= 16; off <<= 1)
        #pragma unroll
        for (int kp = 0; kp < 6; kp++)
            #pragma unroll
            for (int i = 0; i < 2; i++)
                acc[kp][i] = add2(acc[kp][i], __shfl_xor_sync(0xffffffffu, acc[kp][i], off));

    if (es == 0) {
        #pragma unroll
        for (int i = 0; i < 2; i++) {
            int r = rr0 + 8 * i;
            if (r < 140) {
                #pragma unroll
                for (int kp = 0; kp < 6; kp++) {
                    float s0, s1; unpack2(s0, s1, acc[kp][i]);
                    scores[(2 * kp) * 144 + r]     = s0;
                    scores[(2 * kp + 1) * 144 + r] = s1;
                }
            }
        }
    }
    __syncthreads();

    // per-k logsumexp over [pos, 128 negs]; 9 warps cover 12 k
    for (int k = wp; k < K_; k += 9) {
        float v[4], mx = -1e30f;
        #pragma unroll
        for (int q = 0; q < 4; q++) {
            v[q] = scores[k * 144 + lane + q * 32] * INV_E;
            mx = fmaxf(mx, v[q]);
        }
        #pragma unroll
        for (int off = 16; off > 0; off >>= 1)
            mx = fmaxf(mx, __shfl_xor_sync(0xffffffffu, mx, off));
        const float pos = scores[k * 144 + 128 + k] * INV_E;
        const float mm = fmaxf(mx, pos);
        float se = 0.f;
        #pragma unroll
        for (int q = 0; q < 4; q++) se += __expf(v[q] - mm);
        #pragma unroll
        for (int off = 16; off > 0; off >>= 1)
            se += __shfl_xor_sync(0xffffffffu, se, off);
        if (lane == 0) {
            float lse = mm + __logf(se + __expf(pos - mm));
            g_part[(size_t)k * M_ + blk]        = lse - pos;
            g_part[(size_t)(12 + k) * M_ + blk] = (pos >= mx) ? 1.f : 0.f;
        }
    }
}

// ---------------------------------------------------------------------------
// kC: 24 blocks x 512 threads, contiguous segment sums
// ---------------------------------------------------------------------------
__global__ __launch_bounds__(512) void kC(float* __restrict__ out) {
    __shared__ float red[16];
    const int j = blockIdx.x;
    const int tid = threadIdx.x, lane = tid & 31, wp = tid >> 5;
    const float* src = g_part + (size_t)j * M_;
    float s = 0.f;
    for (int i = tid; i < M_; i += 512) s += src[i];
    #pragma unroll
    for (int off = 16; off > 0; off >>= 1)
        s += __shfl_xor_sync(0xffffffffu, s, off);
    if (lane == 0) red[wp] = s;
    __syncthreads();
    if (tid < 16) {
        float v = red[tid];
        #pragma unroll
        for (int off = 8; off > 0; off >>= 1)
            v += __shfl_xor_sync(0xffffu, v, off);
        if (tid == 0) out[j] = v * (1.0f / (float)M_);
    }
}

// ---------------------------------------------------------------------------
extern "C" void kernel_launch(void* const* d_in, const int* in_sizes, int n_in,
                              void* d_out, int out_size) {
    const float* cF  = (const float*)d_in[0];
    const float* enc = (const float*)d_in[1];
    const float* Wp  = (const float*)d_in[2];
    const void* eIdx = (const void*)d_in[3];
    float* out = (float*)d_out;

    cudaFuncSetAttribute(kA, cudaFuncAttributeMaxDynamicSharedMemorySize, KA_SMEM);
    cudaFuncSetAttribute(kB, cudaFuncAttributeMaxDynamicSharedMemorySize, KB_SMEM);

    kP<<<A_CTAS + 384, 256>>>(cF, Wp);
    dim3 gA(MT_, 2, K_);
    kA<<<gA, 256, KA_SMEM>>>();
    kB<<<M_, 288, KB_SMEM>>>(enc, eIdx);
    kC<<<24, 512>>>(out);
}